// round 2
// baseline (speedup 1.0000x reference)
#include <cuda_runtime.h>

// LSTM autoencoder, fully fused single kernel.
// B=4096, T=512, F=8, H=16.
// Layout: one half-warp (16 lanes) per batch element; lane = hidden unit.
// All weights register-resident; h shared via width-16 warp shuffles.
// Decoder input projection is constant per batch (input = repeated hT) -> hoisted.
// Output head fused into decoder h-broadcast loop.

#define B_ 4096
#define T_ 512
#define F_ 8
#define H_ 16

__device__ __forceinline__ float fsigmoid(float x) {
    // 1/(1+e^-x): MUFU.EX2 + MUFU.RCP path, ~1e-6 rel err
    float e = __expf(-x);
    return __fdividef(1.0f, 1.0f + e);
}
__device__ __forceinline__ float ftanh(float x) {
    // tanh = 1 - 2/(e^{2x}+1); handles +-inf of expf correctly
    float e = __expf(2.0f * x);
    return 1.0f - __fdividef(2.0f, 1.0f + e);
}

__global__ __launch_bounds__(128)
void lstm_ae_kernel(const float* __restrict__ x,
                    const float* __restrict__ eWih, const float* __restrict__ eWhh,
                    const float* __restrict__ ebih, const float* __restrict__ ebhh,
                    const float* __restrict__ dWih, const float* __restrict__ dWhh,
                    const float* __restrict__ dbih, const float* __restrict__ dbhh,
                    const float* __restrict__ oW,  const float* __restrict__ ob,
                    float* __restrict__ out)
{
    const int tid = blockIdx.x * blockDim.x + threadIdx.x;
    const int b   = tid >> 4;     // batch element (half-warp)
    const int u   = tid & 15;     // hidden unit handled by this lane
    const unsigned FULL = 0xffffffffu;
    if (b >= B_) return;          // grid is exact; whole warps only

    // ---------------- encoder weights (register resident) ----------------
    float wih[4][8];   // input->gate rows for unit u, gates i,f,g,o
    float whh[4][16];  // hidden->gate rows
    float bias[4];
    #pragma unroll
    for (int g = 0; g < 4; ++g) {
        const int r = g * H_ + u;
        bias[g] = ebih[r] + ebhh[r];
        #pragma unroll
        for (int f = 0; f < F_; ++f) wih[g][f] = eWih[r * F_ + f];
        #pragma unroll
        for (int k = 0; k < H_; ++k) whh[g][k] = eWhh[r * H_ + k];
    }

    // ---------------- encoder recurrence ----------------
    float h = 0.0f, c = 0.0f;
    const float4* xp = reinterpret_cast<const float4*>(x + (size_t)b * T_ * F_);
    float4 xa = __ldg(xp + 0);
    float4 xb = __ldg(xp + 1);

    for (int t = 0; t < T_; ++t) {
        float4 na, nb;
        if (t + 1 < T_) {                       // prefetch next step
            na = __ldg(xp + 2 * (t + 1));
            nb = __ldg(xp + 2 * (t + 1) + 1);
        }
        float a0 = bias[0], a1 = bias[1], a2 = bias[2], a3 = bias[3];

        // input projection: 8 features
        {
            float xv0=xa.x, xv1=xa.y, xv2=xa.z, xv3=xa.w;
            float xv4=xb.x, xv5=xb.y, xv6=xb.z, xv7=xb.w;
            a0 += xv0*wih[0][0]+xv1*wih[0][1]+xv2*wih[0][2]+xv3*wih[0][3]
                 +xv4*wih[0][4]+xv5*wih[0][5]+xv6*wih[0][6]+xv7*wih[0][7];
            a1 += xv0*wih[1][0]+xv1*wih[1][1]+xv2*wih[1][2]+xv3*wih[1][3]
                 +xv4*wih[1][4]+xv5*wih[1][5]+xv6*wih[1][6]+xv7*wih[1][7];
            a2 += xv0*wih[2][0]+xv1*wih[2][1]+xv2*wih[2][2]+xv3*wih[2][3]
                 +xv4*wih[2][4]+xv5*wih[2][5]+xv6*wih[2][6]+xv7*wih[2][7];
            a3 += xv0*wih[3][0]+xv1*wih[3][1]+xv2*wih[3][2]+xv3*wih[3][3]
                 +xv4*wih[3][4]+xv5*wih[3][5]+xv6*wih[3][6]+xv7*wih[3][7];
        }

        // recurrent projection: broadcast h_k across the half-warp
        #pragma unroll
        for (int k = 0; k < H_; ++k) {
            float hk = __shfl_sync(FULL, h, k, 16);
            a0 += hk * whh[0][k];
            a1 += hk * whh[1][k];
            a2 += hk * whh[2][k];
            a3 += hk * whh[3][k];
        }

        float ig = fsigmoid(a0);
        float fg = fsigmoid(a1);
        float gg = ftanh(a2);
        float og = fsigmoid(a3);
        c = fg * c + ig * gg;
        h = og * ftanh(c);

        xa = na; xb = nb;
    }

    // ---------------- decoder setup ----------------
    // Input is constant (hT repeated) -> input projection hoisted out of the loop.
    float xpg[4];
    #pragma unroll
    for (int g = 0; g < 4; ++g) {
        const int r = g * H_ + u;
        float a = dbih[r] + dbhh[r];
        #pragma unroll
        for (int k = 0; k < H_; ++k) {
            float hk = __shfl_sync(FULL, h, k, 16);
            a += hk * __ldg(&dWih[r * H_ + k]);
        }
        xpg[g] = a;
        #pragma unroll
        for (int k = 0; k < H_; ++k) whh[g][k] = dWhh[r * H_ + k];  // reuse regs
    }

    // output head: every lane computes output feature (u & 7); lanes 0-7 store
    float ow[16];
    const int fo = u & 7;
    #pragma unroll
    for (int k = 0; k < H_; ++k) ow[k] = __ldg(&oW[fo * H_ + k]);
    const float obv = __ldg(&ob[fo]);

    // ---------------- decoder recurrence + fused projection ----------------
    h = 0.0f; c = 0.0f;
    float* outp = out + (size_t)b * T_ * F_;

    for (int t = 0; t < T_; ++t) {
        float a0 = xpg[0], a1 = xpg[1], a2 = xpg[2], a3 = xpg[3];
        float oacc = obv;
        #pragma unroll
        for (int k = 0; k < H_; ++k) {
            float hk = __shfl_sync(FULL, h, k, 16);   // h_{t-1}
            a0 += hk * whh[0][k];
            a1 += hk * whh[1][k];
            a2 += hk * whh[2][k];
            a3 += hk * whh[3][k];
            oacc += hk * ow[k];                        // projection of h_{t-1}
        }
        if (t > 0 && u < 8) outp[(t - 1) * F_ + u] = oacc;   // decoded[t-1] @ oW^T

        float ig = fsigmoid(a0);
        float fg = fsigmoid(a1);
        float gg = ftanh(a2);
        float og = fsigmoid(a3);
        c = fg * c + ig * gg;
        h = og * ftanh(c);
    }

    // final timestep projection (decoded[T-1])
    {
        float oacc = obv;
        #pragma unroll
        for (int k = 0; k < H_; ++k) {
            float hk = __shfl_sync(FULL, h, k, 16);
            oacc += hk * ow[k];
        }
        if (u < 8) outp[(T_ - 1) * F_ + u] = oacc;
    }
}

extern "C" void kernel_launch(void* const* d_in, const int* in_sizes, int n_in,
                              void* d_out, int out_size)
{
    const float* x     = (const float*)d_in[0];
    const float* eWih  = (const float*)d_in[1];
    const float* eWhh  = (const float*)d_in[2];
    const float* ebih  = (const float*)d_in[3];
    const float* ebhh  = (const float*)d_in[4];
    const float* dWih  = (const float*)d_in[5];
    const float* dWhh  = (const float*)d_in[6];
    const float* dbih  = (const float*)d_in[7];
    const float* dbhh  = (const float*)d_in[8];
    const float* oW    = (const float*)d_in[9];
    const float* ob    = (const float*)d_in[10];
    float* out = (float*)d_out;

    // 4096 batches * 16 lanes = 65536 threads; 128/block -> 512 blocks (exact)
    lstm_ae_kernel<<<512, 128>>>(x, eWih, eWhh, ebih, ebhh,
                                 dWih, dWhh, dbih, dbhh, oW, ob, out);
}

// round 3
// speedup vs baseline: 1.0424x; 1.0424x over previous
#include <cuda_runtime.h>

// LSTM autoencoder, fully fused. B=4096, T=512, F=8, H=16.
// Half-warp (16 lanes) per batch element, lane = hidden unit.
// R2: f32x2 packed FFMA (k-pairs), smem double-buffered h broadcast
// (LDS.128 -> aligned pairs, zero-cost packing), MUFU.TANH for tanh gates.

#define B_ 4096
#define T_ 512
#define F_ 8
#define H_ 16

typedef unsigned long long u64;

__device__ __forceinline__ u64 pk2(float lo, float hi) {
    u64 r; asm("mov.b64 %0,{%1,%2};" : "=l"(r) : "f"(lo), "f"(hi)); return r;
}
__device__ __forceinline__ void fma2(u64& d, u64 a, u64 b) {
    asm("fma.rn.f32x2 %0,%1,%2,%0;" : "+l"(d) : "l"(a), "l"(b));
}
__device__ __forceinline__ float hadd2(u64 v) {
    float lo, hi; asm("mov.b64 {%0,%1},%2;" : "=f"(lo), "=f"(hi) : "l"(v));
    return lo + hi;
}
__device__ __forceinline__ float tanh_fast(float x) {
    float r; asm("tanh.approx.f32 %0,%1;" : "=f"(r) : "f"(x)); return r;
}
__device__ __forceinline__ float sigm(float x) {
    float e = __expf(-x);
    return __fdividef(1.0f, 1.0f + e);
}

__global__ __launch_bounds__(128, 4)
void lstm_ae_kernel(const float* __restrict__ x,
                    const float* __restrict__ eWih, const float* __restrict__ eWhh,
                    const float* __restrict__ ebih, const float* __restrict__ ebhh,
                    const float* __restrict__ dWih, const float* __restrict__ dWhh,
                    const float* __restrict__ dbih, const float* __restrict__ dbhh,
                    const float* __restrict__ oW,  const float* __restrict__ ob,
                    float* __restrict__ out)
{
    const int tid = blockIdx.x * blockDim.x + threadIdx.x;
    const int b   = tid >> 4;            // batch element
    const int u   = tid & 15;            // hidden unit
    const int e   = threadIdx.x >> 4;    // element slot within block (0..7)

    // h broadcast buffers: [elem][buf][16 used + 4 pad] -> elem stride 40 floats
    // (160B, 16B-aligned, shifts banks by 8 between half-warps)
    __shared__ __align__(16) float sm[8][2][20];

    // ---------------- encoder weights (packed pairs, register resident) -----
    u64 wh[4][8];     // hidden->gate rows, k-pairs
    u64 wi[4][4];     // input->gate rows, f-pairs
    float bias[4];
    #pragma unroll
    for (int g = 0; g < 4; ++g) {
        const int r = g * H_ + u;
        bias[g] = ebih[r] + ebhh[r];
        #pragma unroll
        for (int j = 0; j < 8; ++j)
            wh[g][j] = pk2(eWhh[r * H_ + 2 * j], eWhh[r * H_ + 2 * j + 1]);
        #pragma unroll
        for (int j = 0; j < 4; ++j)
            wi[g][j] = pk2(eWih[r * F_ + 2 * j], eWih[r * F_ + 2 * j + 1]);
    }

    float h = 0.0f, c = 0.0f;
    sm[e][0][u] = 0.0f;
    __syncwarp();

    const float4* xp4 = reinterpret_cast<const float4*>(x + (size_t)b * T_ * F_);

    // ---------------- encoder recurrence ----------------
    #define ESTEP(t, RB, WB) { \
        float4 xa = __ldg(xp4 + 2 * (t)); \
        float4 xb = __ldg(xp4 + 2 * (t) + 1); \
        u64 a0 = pk2(bias[0], 0.f), a1 = pk2(bias[1], 0.f); \
        u64 a2 = pk2(bias[2], 0.f), a3 = pk2(bias[3], 0.f); \
        u64 q; \
        q = pk2(xa.x, xa.y); fma2(a0,q,wi[0][0]); fma2(a1,q,wi[1][0]); fma2(a2,q,wi[2][0]); fma2(a3,q,wi[3][0]); \
        q = pk2(xa.z, xa.w); fma2(a0,q,wi[0][1]); fma2(a1,q,wi[1][1]); fma2(a2,q,wi[2][1]); fma2(a3,q,wi[3][1]); \
        q = pk2(xb.x, xb.y); fma2(a0,q,wi[0][2]); fma2(a1,q,wi[1][2]); fma2(a2,q,wi[2][2]); fma2(a3,q,wi[3][2]); \
        q = pk2(xb.z, xb.w); fma2(a0,q,wi[0][3]); fma2(a1,q,wi[1][3]); fma2(a2,q,wi[2][3]); fma2(a3,q,wi[3][3]); \
        const float4* hb = reinterpret_cast<const float4*>(&sm[e][RB][0]); \
        _Pragma("unroll") \
        for (int j = 0; j < 4; ++j) { \
            float4 hq = hb[j]; \
            u64 p0 = pk2(hq.x, hq.y), p1 = pk2(hq.z, hq.w); \
            fma2(a0,p0,wh[0][2*j]);   fma2(a1,p0,wh[1][2*j]);   fma2(a2,p0,wh[2][2*j]);   fma2(a3,p0,wh[3][2*j]); \
            fma2(a0,p1,wh[0][2*j+1]); fma2(a1,p1,wh[1][2*j+1]); fma2(a2,p1,wh[2][2*j+1]); fma2(a3,p1,wh[3][2*j+1]); \
        } \
        float ig = sigm(hadd2(a0)); \
        float fg = sigm(hadd2(a1)); \
        float gg = tanh_fast(hadd2(a2)); \
        float og = sigm(hadd2(a3)); \
        c = fg * c + ig * gg; \
        h = og * tanh_fast(c); \
        sm[e][WB][u] = h; \
        __syncwarp(); }

    for (int t = 0; t < T_; t += 2) {
        ESTEP(t,     0, 1)
        ESTEP(t + 1, 1, 0)
    }
    // final encoder h vector now lives in buf 0

    // ---------------- decoder setup ----------------
    // Input is hT repeated -> input projection is a per-batch constant.
    float xpg[4];
    #pragma unroll
    for (int g = 0; g < 4; ++g) {
        const int r = g * H_ + u;
        float a = dbih[r] + dbhh[r];
        #pragma unroll
        for (int k = 0; k < H_; ++k)
            a += sm[e][0][k] * __ldg(&dWih[r * H_ + k]);
        xpg[g] = a;
        #pragma unroll
        for (int j = 0; j < 8; ++j)
            wh[g][j] = pk2(dWhh[r * H_ + 2 * j], dWhh[r * H_ + 2 * j + 1]);
    }
    // output head: lane computes feature (u&7); lanes 0-7 store
    u64 ow[8];
    const int fo = u & 7;
    #pragma unroll
    for (int j = 0; j < 8; ++j)
        ow[j] = pk2(oW[fo * H_ + 2 * j], oW[fo * H_ + 2 * j + 1]);
    const float obv = __ldg(&ob[fo]);

    __syncwarp();               // everyone done reading hT from buf 0
    sm[e][0][u] = 0.0f;         // decoder h0 = 0
    h = 0.0f; c = 0.0f;
    __syncwarp();

    float* outp = out + (size_t)b * T_ * F_;

    // ---------------- decoder recurrence + fused output head ----------------
    #define DSTEP(t, RB, WB) { \
        u64 a0 = pk2(xpg[0], 0.f), a1 = pk2(xpg[1], 0.f); \
        u64 a2 = pk2(xpg[2], 0.f), a3 = pk2(xpg[3], 0.f); \
        u64 oa = pk2(obv, 0.f); \
        const float4* hb = reinterpret_cast<const float4*>(&sm[e][RB][0]); \
        _Pragma("unroll") \
        for (int j = 0; j < 4; ++j) { \
            float4 hq = hb[j]; \
            u64 p0 = pk2(hq.x, hq.y), p1 = pk2(hq.z, hq.w); \
            fma2(a0,p0,wh[0][2*j]);   fma2(a1,p0,wh[1][2*j]);   fma2(a2,p0,wh[2][2*j]);   fma2(a3,p0,wh[3][2*j]); \
            fma2(oa,p0,ow[2*j]); \
            fma2(a0,p1,wh[0][2*j+1]); fma2(a1,p1,wh[1][2*j+1]); fma2(a2,p1,wh[2][2*j+1]); fma2(a3,p1,wh[3][2*j+1]); \
            fma2(oa,p1,ow[2*j+1]); \
        } \
        if ((t) > 0 && u < 8) outp[((t) - 1) * F_ + u] = hadd2(oa); \
        float ig = sigm(hadd2(a0)); \
        float fg = sigm(hadd2(a1)); \
        float gg = tanh_fast(hadd2(a2)); \
        float og = sigm(hadd2(a3)); \
        c = fg * c + ig * gg; \
        h = og * tanh_fast(c); \
        sm[e][WB][u] = h; \
        __syncwarp(); }

    for (int t = 0; t < T_; t += 2) {
        DSTEP(t,     0, 1)
        DSTEP(t + 1, 1, 0)
    }

    // epilogue: project decoded[T-1] (final h, buf 0)
    {
        u64 oa = pk2(obv, 0.f);
        const float4* hb = reinterpret_cast<const float4*>(&sm[e][0][0]);
        #pragma unroll
        for (int j = 0; j < 4; ++j) {
            float4 hq = hb[j];
            u64 p0 = pk2(hq.x, hq.y), p1 = pk2(hq.z, hq.w);
            fma2(oa, p0, ow[2 * j]);
            fma2(oa, p1, ow[2 * j + 1]);
        }
        if (u < 8) outp[(T_ - 1) * F_ + u] = hadd2(oa);
    }
}

extern "C" void kernel_launch(void* const* d_in, const int* in_sizes, int n_in,
                              void* d_out, int out_size)
{
    const float* x    = (const float*)d_in[0];
    const float* eWih = (const float*)d_in[1];
    const float* eWhh = (const float*)d_in[2];
    const float* ebih = (const float*)d_in[3];
    const float* ebhh = (const float*)d_in[4];
    const float* dWih = (const float*)d_in[5];
    const float* dWhh = (const float*)d_in[6];
    const float* dbih = (const float*)d_in[7];
    const float* dbhh = (const float*)d_in[8];
    const float* oW   = (const float*)d_in[9];
    const float* ob   = (const float*)d_in[10];
    float* out = (float*)d_out;

    lstm_ae_kernel<<<512, 128>>>(x, eWih, eWhh, ebih, ebhh,
                                 dWih, dWhh, dbih, dbhh, oW, ob, out);
}

// round 4
// speedup vs baseline: 1.1239x; 1.0781x over previous
#include <cuda_runtime.h>

// LSTM autoencoder, fully fused. B=4096, T=512, F=8, H=16.
// Half-warp (16 lanes) per batch element, lane = hidden unit.
// R3: latency attack — x line prefetch, no __syncwarp (volatile-asm smem ordering),
// packed ld.shared.v2.u64 h loads (zero repack movs), tanh-based sigmoids.

#define B_ 4096
#define T_ 512
#define F_ 8
#define H_ 16

typedef unsigned long long u64;

__device__ __forceinline__ u64 pk2(float lo, float hi) {
    u64 r; asm("mov.b64 %0,{%1,%2};" : "=l"(r) : "f"(lo), "f"(hi)); return r;
}
__device__ __forceinline__ void fma2(u64& d, u64 a, u64 b) {
    asm("fma.rn.f32x2 %0,%1,%2,%0;" : "+l"(d) : "l"(a), "l"(b));
}
__device__ __forceinline__ float hadd2(u64 v) {
    float lo, hi; asm("mov.b64 {%0,%1},%2;" : "=f"(lo), "=f"(hi) : "l"(v));
    return lo + hi;
}
__device__ __forceinline__ float tanh_fast(float x) {
    float r; asm("tanh.approx.f32 %0,%1;" : "=f"(r) : "f"(x)); return r;
}
// sigmoid(x) = 0.5*tanh(x/2) + 0.5  (1 MUFU, 24-cyc chain)
__device__ __forceinline__ float sigm(float x) {
    return __fmaf_rn(0.5f, tanh_fast(0.5f * x), 0.5f);
}
// ordered (volatile) smem ops — program-order within a warp replaces __syncwarp
__device__ __forceinline__ void lds2(u64& a, u64& b, unsigned addr) {
    asm volatile("ld.shared.v2.u64 {%0,%1},[%2];" : "=l"(a), "=l"(b) : "r"(addr));
}
__device__ __forceinline__ void sts1(unsigned addr, float v) {
    asm volatile("st.shared.b32 [%0],%1;" :: "r"(addr), "f"(v));
}
__device__ __forceinline__ void ldg2(u64& a, u64& b, const float* p) {
    asm volatile("ld.global.nc.v2.u64 {%0,%1},[%2];" : "=l"(a), "=l"(b) : "l"(p));
}
__device__ __forceinline__ void prefetch_l1(const float* p) {
    float d; asm volatile("ld.global.nc.b32 %0,[%1];" : "=f"(d) : "l"(p));
}
#define CBAR() asm volatile("" ::: "memory")

__global__ __launch_bounds__(128, 4)
void lstm_ae_kernel(const float* __restrict__ x,
                    const float* __restrict__ eWih, const float* __restrict__ eWhh,
                    const float* __restrict__ ebih, const float* __restrict__ ebhh,
                    const float* __restrict__ dWih, const float* __restrict__ dWhh,
                    const float* __restrict__ dbih, const float* __restrict__ dbhh,
                    const float* __restrict__ oW,  const float* __restrict__ ob,
                    float* __restrict__ out)
{
    const int tid = blockIdx.x * blockDim.x + threadIdx.x;
    const int b   = tid >> 4;            // batch element
    const int u   = tid & 15;            // hidden unit
    const int e   = threadIdx.x >> 4;    // half-warp slot in block (0..7)

    // [elem][buf][24]: e-stride 48 words (bank +16 between half-warps of a warp
    // -> zero LDS/STS conflicts), buf stride 96B (16B aligned).
    __shared__ __align__(16) float sm[8][2][24];

    const unsigned hb0 = (unsigned)__cvta_generic_to_shared(&sm[e][0][0]);
    const unsigned hb1 = hb0 + 96;

    // ---------------- encoder weights (packed pairs, register resident) -----
    u64 wh[4][8];     // hidden->gate rows, k-pairs
    u64 wi[4][4];     // input->gate rows, f-pairs
    float bias[4];
    #pragma unroll
    for (int g = 0; g < 4; ++g) {
        const int r = g * H_ + u;
        bias[g] = ebih[r] + ebhh[r];
        #pragma unroll
        for (int j = 0; j < 8; ++j)
            wh[g][j] = pk2(eWhh[r * H_ + 2 * j], eWhh[r * H_ + 2 * j + 1]);
        #pragma unroll
        for (int j = 0; j < 4; ++j)
            wi[g][j] = pk2(eWih[r * F_ + 2 * j], eWih[r * F_ + 2 * j + 1]);
    }

    float h = 0.0f, c = 0.0f;
    sm[e][0][u] = 0.0f;
    CBAR();

    const float* xrow = x + (size_t)b * T_ * F_;
    prefetch_l1(xrow);                     // warm first line

    // ---------------- encoder recurrence ----------------
    #define ESTEP(t, RA, WA) { \
        int tp = ((t) + 2 < T_) ? ((t) + 2) : (T_ - 1); \
        prefetch_l1(xrow + tp * F_); \
        u64 a0 = pk2(bias[0], 0.f), a1 = pk2(bias[1], 0.f); \
        u64 a2 = pk2(bias[2], 0.f), a3 = pk2(bias[3], 0.f); \
        u64 xq0, xq1, xq2, xq3; \
        ldg2(xq0, xq1, xrow + (t) * F_); \
        fma2(a0,xq0,wi[0][0]); fma2(a1,xq0,wi[1][0]); fma2(a2,xq0,wi[2][0]); fma2(a3,xq0,wi[3][0]); \
        fma2(a0,xq1,wi[0][1]); fma2(a1,xq1,wi[1][1]); fma2(a2,xq1,wi[2][1]); fma2(a3,xq1,wi[3][1]); \
        ldg2(xq2, xq3, xrow + (t) * F_ + 4); \
        fma2(a0,xq2,wi[0][2]); fma2(a1,xq2,wi[1][2]); fma2(a2,xq2,wi[2][2]); fma2(a3,xq2,wi[3][2]); \
        fma2(a0,xq3,wi[0][3]); fma2(a1,xq3,wi[1][3]); fma2(a2,xq3,wi[2][3]); fma2(a3,xq3,wi[3][3]); \
        u64 p0,p1,p2,p3,p4,p5,p6,p7; \
        lds2(p0, p1, RA);      lds2(p2, p3, RA + 16); \
        lds2(p4, p5, RA + 32); lds2(p6, p7, RA + 48); \
        fma2(a0,p0,wh[0][0]); fma2(a1,p0,wh[1][0]); fma2(a2,p0,wh[2][0]); fma2(a3,p0,wh[3][0]); \
        fma2(a0,p1,wh[0][1]); fma2(a1,p1,wh[1][1]); fma2(a2,p1,wh[2][1]); fma2(a3,p1,wh[3][1]); \
        fma2(a0,p2,wh[0][2]); fma2(a1,p2,wh[1][2]); fma2(a2,p2,wh[2][2]); fma2(a3,p2,wh[3][2]); \
        fma2(a0,p3,wh[0][3]); fma2(a1,p3,wh[1][3]); fma2(a2,p3,wh[2][3]); fma2(a3,p3,wh[3][3]); \
        fma2(a0,p4,wh[0][4]); fma2(a1,p4,wh[1][4]); fma2(a2,p4,wh[2][4]); fma2(a3,p4,wh[3][4]); \
        fma2(a0,p5,wh[0][5]); fma2(a1,p5,wh[1][5]); fma2(a2,p5,wh[2][5]); fma2(a3,p5,wh[3][5]); \
        fma2(a0,p6,wh[0][6]); fma2(a1,p6,wh[1][6]); fma2(a2,p6,wh[2][6]); fma2(a3,p6,wh[3][6]); \
        fma2(a0,p7,wh[0][7]); fma2(a1,p7,wh[1][7]); fma2(a2,p7,wh[2][7]); fma2(a3,p7,wh[3][7]); \
        float ig = sigm(hadd2(a0)); \
        float fg = sigm(hadd2(a1)); \
        float gg = tanh_fast(hadd2(a2)); \
        float og = sigm(hadd2(a3)); \
        c = __fmaf_rn(fg, c, ig * gg); \
        h = og * tanh_fast(c); \
        sts1((WA) + u * 4, h); }

    for (int t = 0; t < T_; t += 2) {
        ESTEP(t,     hb0, hb1)
        ESTEP(t + 1, hb1, hb0)
    }
    CBAR();
    // final encoder h vector is in buf 0

    // ---------------- decoder setup ----------------
    // Input is hT repeated -> input projection is a per-batch constant.
    float xpg[4];
    #pragma unroll
    for (int g = 0; g < 4; ++g) {
        const int r = g * H_ + u;
        float a = dbih[r] + dbhh[r];
        #pragma unroll
        for (int k = 0; k < H_; ++k)
            a += sm[e][0][k] * __ldg(&dWih[r * H_ + k]);
        xpg[g] = a;
        #pragma unroll
        for (int j = 0; j < 8; ++j)
            wh[g][j] = pk2(dWhh[r * H_ + 2 * j], dWhh[r * H_ + 2 * j + 1]);  // reuse regs
    }
    // output head: lane computes feature (u&7); lanes 0-7 store
    u64 ow[8];
    const int fo = u & 7;
    #pragma unroll
    for (int j = 0; j < 8; ++j)
        ow[j] = pk2(oW[fo * H_ + 2 * j], oW[fo * H_ + 2 * j + 1]);
    const float obv = __ldg(&ob[fo]);

    CBAR();
    sm[e][0][u] = 0.0f;        // decoder h0 = 0
    h = 0.0f; c = 0.0f;
    CBAR();

    float* outp = out + (size_t)b * T_ * F_;

    // ---------------- decoder recurrence + fused output head ----------------
    #define DSTEP(t, RA, WA) { \
        u64 a0 = pk2(xpg[0], 0.f), a1 = pk2(xpg[1], 0.f); \
        u64 a2 = pk2(xpg[2], 0.f), a3 = pk2(xpg[3], 0.f); \
        u64 oa = pk2(obv, 0.f); \
        u64 p0,p1,p2,p3,p4,p5,p6,p7; \
        lds2(p0, p1, RA);      lds2(p2, p3, RA + 16); \
        lds2(p4, p5, RA + 32); lds2(p6, p7, RA + 48); \
        fma2(a0,p0,wh[0][0]); fma2(a1,p0,wh[1][0]); fma2(a2,p0,wh[2][0]); fma2(a3,p0,wh[3][0]); fma2(oa,p0,ow[0]); \
        fma2(a0,p1,wh[0][1]); fma2(a1,p1,wh[1][1]); fma2(a2,p1,wh[2][1]); fma2(a3,p1,wh[3][1]); fma2(oa,p1,ow[1]); \
        fma2(a0,p2,wh[0][2]); fma2(a1,p2,wh[1][2]); fma2(a2,p2,wh[2][2]); fma2(a3,p2,wh[3][2]); fma2(oa,p2,ow[2]); \
        fma2(a0,p3,wh[0][3]); fma2(a1,p3,wh[1][3]); fma2(a2,p3,wh[2][3]); fma2(a3,p3,wh[3][3]); fma2(oa,p3,ow[3]); \
        fma2(a0,p4,wh[0][4]); fma2(a1,p4,wh[1][4]); fma2(a2,p4,wh[2][4]); fma2(a3,p4,wh[3][4]); fma2(oa,p4,ow[4]); \
        fma2(a0,p5,wh[0][5]); fma2(a1,p5,wh[1][5]); fma2(a2,p5,wh[2][5]); fma2(a3,p5,wh[3][5]); fma2(oa,p5,ow[5]); \
        fma2(a0,p6,wh[0][6]); fma2(a1,p6,wh[1][6]); fma2(a2,p6,wh[2][6]); fma2(a3,p6,wh[3][6]); fma2(oa,p6,ow[6]); \
        fma2(a0,p7,wh[0][7]); fma2(a1,p7,wh[1][7]); fma2(a2,p7,wh[2][7]); fma2(a3,p7,wh[3][7]); fma2(oa,p7,ow[7]); \
        if ((t) > 0 && u < 8) outp[((t) - 1) * F_ + u] = hadd2(oa); \
        float ig = sigm(hadd2(a0)); \
        float fg = sigm(hadd2(a1)); \
        float gg = tanh_fast(hadd2(a2)); \
        float og = sigm(hadd2(a3)); \
        c = __fmaf_rn(fg, c, ig * gg); \
        h = og * tanh_fast(c); \
        sts1((WA) + u * 4, h); }

    for (int t = 0; t < T_; t += 2) {
        DSTEP(t,     hb0, hb1)
        DSTEP(t + 1, hb1, hb0)
    }
    CBAR();

    // epilogue: project decoded[T-1] (final h, buf 0)
    {
        u64 oa = pk2(obv, 0.f);
        u64 p0,p1,p2,p3,p4,p5,p6,p7;
        lds2(p0, p1, hb0);      lds2(p2, p3, hb0 + 16);
        lds2(p4, p5, hb0 + 32); lds2(p6, p7, hb0 + 48);
        fma2(oa,p0,ow[0]); fma2(oa,p1,ow[1]); fma2(oa,p2,ow[2]); fma2(oa,p3,ow[3]);
        fma2(oa,p4,ow[4]); fma2(oa,p5,ow[5]); fma2(oa,p6,ow[6]); fma2(oa,p7,ow[7]);
        if (u < 8) outp[(T_ - 1) * F_ + u] = hadd2(oa);
    }
}

extern "C" void kernel_launch(void* const* d_in, const int* in_sizes, int n_in,
                              void* d_out, int out_size)
{
    const float* x    = (const float*)d_in[0];
    const float* eWih = (const float*)d_in[1];
    const float* eWhh = (const float*)d_in[2];
    const float* ebih = (const float*)d_in[3];
    const float* ebhh = (const float*)d_in[4];
    const float* dWih = (const float*)d_in[5];
    const float* dWhh = (const float*)d_in[6];
    const float* dbih = (const float*)d_in[7];
    const float* dbhh = (const float*)d_in[8];
    const float* oW   = (const float*)d_in[9];
    const float* ob   = (const float*)d_in[10];
    float* out = (float*)d_out;

    lstm_ae_kernel<<<512, 128>>>(x, eWih, eWhh, ebih, ebhh,
                                 dWih, dWhh, dbih, dbhh, oW, ob, out);
}

// round 8
// speedup vs baseline: 1.1406x; 1.0149x over previous
#include <cuda_runtime.h>

// LSTM autoencoder, fully fused. B=4096, T=512, F=8, H=16.
// R4: TWO batch elements per thread (weights register-shared between them)
// -> 2 independent recurrence chains per warp, doubling per-warp ILP to fix
// the 38% issue rate. 16 lanes handle units 0..15 of elements 2p, 2p+1.

#define B_ 4096
#define T_ 512
#define F_ 8
#define H_ 16
#define XOFF (T_ * F_)   // row stride in floats

typedef unsigned long long u64;

__device__ __forceinline__ u64 pk2(float lo, float hi) {
    u64 r; asm("mov.b64 %0,{%1,%2};" : "=l"(r) : "f"(lo), "f"(hi)); return r;
}
__device__ __forceinline__ void fma2(u64& d, u64 a, u64 b) {
    asm("fma.rn.f32x2 %0,%1,%2,%0;" : "+l"(d) : "l"(a), "l"(b));
}
__device__ __forceinline__ float hadd2(u64 v) {
    float lo, hi; asm("mov.b64 {%0,%1},%2;" : "=f"(lo), "=f"(hi) : "l"(v));
    return lo + hi;
}
__device__ __forceinline__ float tanh_fast(float x) {
    float r; asm("tanh.approx.f32 %0,%1;" : "=f"(r) : "f"(x)); return r;
}
__device__ __forceinline__ float sigm(float x) {           // 0.5*tanh(x/2)+0.5
    return __fmaf_rn(0.5f, tanh_fast(0.5f * x), 0.5f);
}
__device__ __forceinline__ void lds2(u64& a, u64& b, unsigned addr) {
    asm volatile("ld.shared.v2.u64 {%0,%1},[%2];" : "=l"(a), "=l"(b) : "r"(addr));
}
__device__ __forceinline__ void sts1(unsigned addr, float v) {
    asm volatile("st.shared.b32 [%0],%1;" :: "r"(addr), "f"(v));
}
__device__ __forceinline__ void ldg2(u64& a, u64& b, const float* p) {
    asm volatile("ld.global.nc.v2.u64 {%0,%1},[%2];" : "=l"(a), "=l"(b) : "l"(p));
}
__device__ __forceinline__ void prefetch_l1(const float* p) {
    float d; asm volatile("ld.global.nc.b32 %0,[%1];" : "=f"(d) : "l"(p));
}
#define CBAR() asm volatile("" ::: "memory")

__global__ __launch_bounds__(128, 2)
void lstm_ae_kernel(const float* __restrict__ x,
                    const float* __restrict__ eWih, const float* __restrict__ eWhh,
                    const float* __restrict__ ebih, const float* __restrict__ ebhh,
                    const float* __restrict__ dWih, const float* __restrict__ dWhh,
                    const float* __restrict__ dbih, const float* __restrict__ dbhh,
                    const float* __restrict__ oW,  const float* __restrict__ ob,
                    float* __restrict__ out)
{
    const int tid  = blockIdx.x * blockDim.x + threadIdx.x;
    const int pr   = tid >> 4;          // batch pair index (0..2047)
    const int u    = tid & 15;          // hidden unit
    const int slot = threadIdx.x >> 4;  // half-warp slot (0..7)

    // Per-slot region 112 floats (448B): slot stride mod 32 banks = 16
    // -> the two half-warps of a warp never collide on STS/LDS banks.
    // Layout inside slot: [buf0 e0: 0..15][buf0 e1: 24..39][buf1 e0: 48..63][buf1 e1: 72..87]
    __shared__ __align__(16) float sm[8][112];
    const unsigned sb = (unsigned)__cvta_generic_to_shared(&sm[slot][0]);
    // byte offsets: e1 = +96, buf1 = +192

    // ---------------- encoder weights (shared by both elements) -------------
    u64 wh[4][8];  u64 wi[4][4];  float bias[4];
    #pragma unroll
    for (int g = 0; g < 4; ++g) {
        const int r = g * H_ + u;
        bias[g] = ebih[r] + ebhh[r];
        #pragma unroll
        for (int j = 0; j < 8; ++j)
            wh[g][j] = pk2(eWhh[r * H_ + 2 * j], eWhh[r * H_ + 2 * j + 1]);
        #pragma unroll
        for (int j = 0; j < 4; ++j)
            wi[g][j] = pk2(eWih[r * F_ + 2 * j], eWih[r * F_ + 2 * j + 1]);
    }

    float h0 = 0.f, c0 = 0.f, h1 = 0.f, c1 = 0.f;
    sm[slot][u] = 0.f;  sm[slot][24 + u] = 0.f;
    CBAR();

    const float* xr = x + (size_t)(2 * pr) * XOFF;   // elem0; elem1 at +XOFF
    prefetch_l1(xr);  prefetch_l1(xr + XOFF);

    // ---------------- encoder recurrence (2 elements interleaved) -----------
    #define ESTEP(t, RO, WO) { \
        int tp = ((t) + 2 < T_) ? ((t) + 2) : (T_ - 1); \
        prefetch_l1(xr + tp * F_); prefetch_l1(xr + XOFF + tp * F_); \
        u64 a0 = pk2(bias[0],0.f), a1 = pk2(bias[1],0.f), a2 = pk2(bias[2],0.f), a3 = pk2(bias[3],0.f); \
        u64 d0 = pk2(bias[0],0.f), d1 = pk2(bias[1],0.f), d2 = pk2(bias[2],0.f), d3 = pk2(bias[3],0.f); \
        u64 x0,x1,x2,x3, y0,y1,y2,y3; \
        ldg2(x0, x1, xr + (t) * F_);          ldg2(x2, x3, xr + (t) * F_ + 4); \
        ldg2(y0, y1, xr + XOFF + (t) * F_);   ldg2(y2, y3, xr + XOFF + (t) * F_ + 4); \
        fma2(a0,x0,wi[0][0]); fma2(d0,y0,wi[0][0]); fma2(a1,x0,wi[1][0]); fma2(d1,y0,wi[1][0]); \
        fma2(a2,x0,wi[2][0]); fma2(d2,y0,wi[2][0]); fma2(a3,x0,wi[3][0]); fma2(d3,y0,wi[3][0]); \
        fma2(a0,x1,wi[0][1]); fma2(d0,y1,wi[0][1]); fma2(a1,x1,wi[1][1]); fma2(d1,y1,wi[1][1]); \
        fma2(a2,x1,wi[2][1]); fma2(d2,y1,wi[2][1]); fma2(a3,x1,wi[3][1]); fma2(d3,y1,wi[3][1]); \
        fma2(a0,x2,wi[0][2]); fma2(d0,y2,wi[0][2]); fma2(a1,x2,wi[1][2]); fma2(d1,y2,wi[1][2]); \
        fma2(a2,x2,wi[2][2]); fma2(d2,y2,wi[2][2]); fma2(a3,x2,wi[3][2]); fma2(d3,y2,wi[3][2]); \
        fma2(a0,x3,wi[0][3]); fma2(d0,y3,wi[0][3]); fma2(a1,x3,wi[1][3]); fma2(d1,y3,wi[1][3]); \
        fma2(a2,x3,wi[2][3]); fma2(d2,y3,wi[2][3]); fma2(a3,x3,wi[3][3]); fma2(d3,y3,wi[3][3]); \
        u64 p0,p1,p2,p3,p4,p5,p6,p7, q0,q1,q2,q3,q4,q5,q6,q7; \
        lds2(p0,p1, sb+(RO));    lds2(p2,p3, sb+(RO)+16); \
        lds2(p4,p5, sb+(RO)+32); lds2(p6,p7, sb+(RO)+48); \
        lds2(q0,q1, sb+(RO)+96); lds2(q2,q3, sb+(RO)+112); \
        lds2(q4,q5, sb+(RO)+128);lds2(q6,q7, sb+(RO)+144); \
        fma2(a0,p0,wh[0][0]); fma2(d0,q0,wh[0][0]); fma2(a1,p0,wh[1][0]); fma2(d1,q0,wh[1][0]); \
        fma2(a2,p0,wh[2][0]); fma2(d2,q0,wh[2][0]); fma2(a3,p0,wh[3][0]); fma2(d3,q0,wh[3][0]); \
        fma2(a0,p1,wh[0][1]); fma2(d0,q1,wh[0][1]); fma2(a1,p1,wh[1][1]); fma2(d1,q1,wh[1][1]); \
        fma2(a2,p1,wh[2][1]); fma2(d2,q1,wh[2][1]); fma2(a3,p1,wh[3][1]); fma2(d3,q1,wh[3][1]); \
        fma2(a0,p2,wh[0][2]); fma2(d0,q2,wh[0][2]); fma2(a1,p2,wh[1][2]); fma2(d1,q2,wh[1][2]); \
        fma2(a2,p2,wh[2][2]); fma2(d2,q2,wh[2][2]); fma2(a3,p2,wh[3][2]); fma2(d3,q2,wh[3][2]); \
        fma2(a0,p3,wh[0][3]); fma2(d0,q3,wh[0][3]); fma2(a1,p3,wh[1][3]); fma2(d1,q3,wh[1][3]); \
        fma2(a2,p3,wh[2][3]); fma2(d2,q3,wh[2][3]); fma2(a3,p3,wh[3][3]); fma2(d3,q3,wh[3][3]); \
        fma2(a0,p4,wh[0][4]); fma2(d0,q4,wh[0][4]); fma2(a1,p4,wh[1][4]); fma2(d1,q4,wh[1][4]); \
        fma2(a2,p4,wh[2][4]); fma2(d2,q4,wh[2][4]); fma2(a3,p4,wh[3][4]); fma2(d3,q4,wh[3][4]); \
        fma2(a0,p5,wh[0][5]); fma2(d0,q5,wh[0][5]); fma2(a1,p5,wh[1][5]); fma2(d1,q5,wh[1][5]); \
        fma2(a2,p5,wh[2][5]); fma2(d2,q5,wh[2][5]); fma2(a3,p5,wh[3][5]); fma2(d3,q5,wh[3][5]); \
        fma2(a0,p6,wh[0][6]); fma2(d0,q6,wh[0][6]); fma2(a1,p6,wh[1][6]); fma2(d1,q6,wh[1][6]); \
        fma2(a2,p6,wh[2][6]); fma2(d2,q6,wh[2][6]); fma2(a3,p6,wh[3][6]); fma2(d3,q6,wh[3][6]); \
        fma2(a0,p7,wh[0][7]); fma2(d0,q7,wh[0][7]); fma2(a1,p7,wh[1][7]); fma2(d1,q7,wh[1][7]); \
        fma2(a2,p7,wh[2][7]); fma2(d2,q7,wh[2][7]); fma2(a3,p7,wh[3][7]); fma2(d3,q7,wh[3][7]); \
        float ig0 = sigm(hadd2(a0)), ig1 = sigm(hadd2(d0)); \
        float fg0 = sigm(hadd2(a1)), fg1 = sigm(hadd2(d1)); \
        float gg0 = tanh_fast(hadd2(a2)), gg1 = tanh_fast(hadd2(d2)); \
        float og0 = sigm(hadd2(a3)), og1 = sigm(hadd2(d3)); \
        c0 = __fmaf_rn(fg0, c0, ig0 * gg0);  c1 = __fmaf_rn(fg1, c1, ig1 * gg1); \
        h0 = og0 * tanh_fast(c0);            h1 = og1 * tanh_fast(c1); \
        sts1(sb + (WO) + u * 4, h0);  sts1(sb + (WO) + 96 + u * 4, h1); }

    for (int t = 0; t < T_; t += 2) {
        ESTEP(t,     0,   192)
        ESTEP(t + 1, 192, 0)
    }
    CBAR();
    // final encoder h of both elements in buf 0 (offsets 0 / 96)

    // ---------------- decoder setup ----------------
    float xpg0[4], xpg1[4];
    #pragma unroll
    for (int g = 0; g < 4; ++g) {
        const int r = g * H_ + u;
        float a = dbih[r] + dbhh[r], bb = a;
        #pragma unroll
        for (int k = 0; k < H_; ++k) {
            float w = __ldg(&dWih[r * H_ + k]);
            a  += sm[slot][k]      * w;
            bb += sm[slot][24 + k] * w;
        }
        xpg0[g] = a;  xpg1[g] = bb;
        #pragma unroll
        for (int j = 0; j < 8; ++j)
            wh[g][j] = pk2(dWhh[r * H_ + 2 * j], dWhh[r * H_ + 2 * j + 1]);  // reuse
    }
    u64 ow[8];
    const int fo = u & 7;
    #pragma unroll
    for (int j = 0; j < 8; ++j)
        ow[j] = pk2(oW[fo * H_ + 2 * j], oW[fo * H_ + 2 * j + 1]);
    const float obv = __ldg(&ob[fo]);

    CBAR();
    sm[slot][u] = 0.f;  sm[slot][24 + u] = 0.f;   // decoder h0 = 0
    h0 = c0 = h1 = c1 = 0.f;
    CBAR();

    float* outp0 = out + (size_t)(2 * pr) * XOFF;
    float* outp1 = outp0 + XOFF;

    // ---------------- decoder recurrence + fused output head ----------------
    #define DSTEP(t, RO, WO) { \
        u64 a0 = pk2(xpg0[0],0.f), a1 = pk2(xpg0[1],0.f), a2 = pk2(xpg0[2],0.f), a3 = pk2(xpg0[3],0.f); \
        u64 d0 = pk2(xpg1[0],0.f), d1 = pk2(xpg1[1],0.f), d2 = pk2(xpg1[2],0.f), d3 = pk2(xpg1[3],0.f); \
        u64 oa = pk2(obv,0.f), oc = pk2(obv,0.f); \
        u64 p0,p1,p2,p3,p4,p5,p6,p7, q0,q1,q2,q3,q4,q5,q6,q7; \
        lds2(p0,p1, sb+(RO));    lds2(p2,p3, sb+(RO)+16); \
        lds2(p4,p5, sb+(RO)+32); lds2(p6,p7, sb+(RO)+48); \
        lds2(q0,q1, sb+(RO)+96); lds2(q2,q3, sb+(RO)+112); \
        lds2(q4,q5, sb+(RO)+128);lds2(q6,q7, sb+(RO)+144); \
        fma2(a0,p0,wh[0][0]); fma2(d0,q0,wh[0][0]); fma2(a1,p0,wh[1][0]); fma2(d1,q0,wh[1][0]); \
        fma2(a2,p0,wh[2][0]); fma2(d2,q0,wh[2][0]); fma2(a3,p0,wh[3][0]); fma2(d3,q0,wh[3][0]); \
        fma2(oa,p0,ow[0]);    fma2(oc,q0,ow[0]); \
        fma2(a0,p1,wh[0][1]); fma2(d0,q1,wh[0][1]); fma2(a1,p1,wh[1][1]); fma2(d1,q1,wh[1][1]); \
        fma2(a2,p1,wh[2][1]); fma2(d2,q1,wh[2][1]); fma2(a3,p1,wh[3][1]); fma2(d3,q1,wh[3][1]); \
        fma2(oa,p1,ow[1]);    fma2(oc,q1,ow[1]); \
        fma2(a0,p2,wh[0][2]); fma2(d0,q2,wh[0][2]); fma2(a1,p2,wh[1][2]); fma2(d1,q2,wh[1][2]); \
        fma2(a2,p2,wh[2][2]); fma2(d2,q2,wh[2][2]); fma2(a3,p2,wh[3][2]); fma2(d3,q2,wh[3][2]); \
        fma2(oa,p2,ow[2]);    fma2(oc,q2,ow[2]); \
        fma2(a0,p3,wh[0][3]); fma2(d0,q3,wh[0][3]); fma2(a1,p3,wh[1][3]); fma2(d1,q3,wh[1][3]); \
        fma2(a2,p3,wh[2][3]); fma2(d2,q3,wh[2][3]); fma2(a3,p3,wh[3][3]); fma2(d3,q3,wh[3][3]); \
        fma2(oa,p3,ow[3]);    fma2(oc,q3,ow[3]); \
        fma2(a0,p4,wh[0][4]); fma2(d0,q4,wh[0][4]); fma2(a1,p4,wh[1][4]); fma2(d1,q4,wh[1][4]); \
        fma2(a2,p4,wh[2][4]); fma2(d2,q4,wh[2][4]); fma2(a3,p4,wh[3][4]); fma2(d3,q4,wh[3][4]); \
        fma2(oa,p4,ow[4]);    fma2(oc,q4,ow[4]); \
        fma2(a0,p5,wh[0][5]); fma2(d0,q5,wh[0][5]); fma2(a1,p5,wh[1][5]); fma2(d1,q5,wh[1][5]); \
        fma2(a2,p5,wh[2][5]); fma2(d2,q5,wh[2][5]); fma2(a3,p5,wh[3][5]); fma2(d3,q5,wh[3][5]); \
        fma2(oa,p5,ow[5]);    fma2(oc,q5,ow[5]); \
        fma2(a0,p6,wh[0][6]); fma2(d0,q6,wh[0][6]); fma2(a1,p6,wh[1][6]); fma2(d1,q6,wh[1][6]); \
        fma2(a2,p6,wh[2][6]); fma2(d2,q6,wh[2][6]); fma2(a3,p6,wh[3][6]); fma2(d3,q6,wh[3][6]); \
        fma2(oa,p6,ow[6]);    fma2(oc,q6,ow[6]); \
        fma2(a0,p7,wh[0][7]); fma2(d0,q7,wh[0][7]); fma2(a1,p7,wh[1][7]); fma2(d1,q7,wh[1][7]); \
        fma2(a2,p7,wh[2][7]); fma2(d2,q7,wh[2][7]); fma2(a3,p7,wh[3][7]); fma2(d3,q7,wh[3][7]); \
        fma2(oa,p7,ow[7]);    fma2(oc,q7,ow[7]); \
        if ((t) > 0 && u < 8) { \
            outp0[((t) - 1) * F_ + u] = hadd2(oa); \
            outp1[((t) - 1) * F_ + u] = hadd2(oc); \
        } \
        float ig0 = sigm(hadd2(a0)), ig1 = sigm(hadd2(d0)); \
        float fg0 = sigm(hadd2(a1)), fg1 = sigm(hadd2(d1)); \
        float gg0 = tanh_fast(hadd2(a2)), gg1 = tanh_fast(hadd2(d2)); \
        float og0 = sigm(hadd2(a3)), og1 = sigm(hadd2(d3)); \
        c0 = __fmaf_rn(fg0, c0, ig0 * gg0);  c1 = __fmaf_rn(fg1, c1, ig1 * gg1); \
        h0 = og0 * tanh_fast(c0);            h1 = og1 * tanh_fast(c1); \
        sts1(sb + (WO) + u * 4, h0);  sts1(sb + (WO) + 96 + u * 4, h1); }

    for (int t = 0; t < T_; t += 2) {
        DSTEP(t,     0,   192)
        DSTEP(t + 1, 192, 0)
    }
    CBAR();

    // epilogue: project decoded[T-1] for both elements (h in buf 0)
    {
        u64 oa = pk2(obv, 0.f), oc = pk2(obv, 0.f);
        u64 p0,p1,p2,p3,p4,p5,p6,p7, q0,q1,q2,q3,q4,q5,q6,q7;
        lds2(p0,p1, sb);      lds2(p2,p3, sb + 16);
        lds2(p4,p5, sb + 32); lds2(p6,p7, sb + 48);
        lds2(q0,q1, sb + 96); lds2(q2,q3, sb + 112);
        lds2(q4,q5, sb + 128);lds2(q6,q7, sb + 144);
        fma2(oa,p0,ow[0]); fma2(oc,q0,ow[0]); fma2(oa,p1,ow[1]); fma2(oc,q1,ow[1]);
        fma2(oa,p2,ow[2]); fma2(oc,q2,ow[2]); fma2(oa,p3,ow[3]); fma2(oc,q3,ow[3]);
        fma2(oa,p4,ow[4]); fma2(oc,q4,ow[4]); fma2(oa,p5,ow[5]); fma2(oc,q5,ow[5]);
        fma2(oa,p6,ow[6]); fma2(oc,q6,ow[6]); fma2(oa,p7,ow[7]); fma2(oc,q7,ow[7]);
        if (u < 8) {
            outp0[(T_ - 1) * F_ + u] = hadd2(oa);
            outp1[(T_ - 1) * F_ + u] = hadd2(oc);
        }
    }
}

extern "C" void kernel_launch(void* const* d_in, const int* in_sizes, int n_in,
                              void* d_out, int out_size)
{
    const float* x    = (const float*)d_in[0];
    const float* eWih = (const float*)d_in[1];
    const float* eWhh = (const float*)d_in[2];
    const float* ebih = (const float*)d_in[3];
    const float* ebhh = (const float*)d_in[4];
    const float* dWih = (const float*)d_in[5];
    const float* dWhh = (const float*)d_in[6];
    const float* dbih = (const float*)d_in[7];
    const float* dbhh = (const float*)d_in[8];
    const float* oW   = (const float*)d_in[9];
    const float* ob   = (const float*)d_in[10];
    float* out = (float*)d_out;

    // 2048 batch pairs * 16 lanes = 32768 threads; 128/block -> 256 blocks
    lstm_ae_kernel<<<256, 128>>>(x, eWih, eWhh, ebih, ebhh,
                                 dWih, dWhh, dbih, dbhh, oW, ob, out);
}